// round 14
// baseline (speedup 1.0000x reference)
#include <cuda_runtime.h>
#include <cuda_fp16.h>
#include <cstdint>

// ============ target-safe warp-MMA primitives (sm_80+ features only) ============

__device__ __forceinline__ uint32_t smem_to_u32(const void* smem_ptr) {
    uint32_t addr;
    asm("{ .reg .u64 tmp; cvta.to.shared.u64 tmp, %1; cvt.u32.u64 %0, tmp; }"
        : "=r"(addr) : "l"(smem_ptr));
    return addr;
}

#define LDSM_X4(r0, r1, r2, r3, addr) \
    asm volatile("ldmatrix.sync.aligned.m8n8.x4.shared.b16 {%0,%1,%2,%3}, [%4];" \
        : "=r"(r0), "=r"(r1), "=r"(r2), "=r"(r3) : "r"(addr))

#define MMA_16816(d, a0, a1, a2, a3, b0, b1) \
    asm volatile("mma.sync.aligned.m16n8k16.row.col.f32.f16.f16.f32 " \
        "{%0,%1,%2,%3}, {%4,%5,%6,%7}, {%8,%9}, {%0,%1,%2,%3};" \
        : "+f"((d)[0]), "+f"((d)[1]), "+f"((d)[2]), "+f"((d)[3]) \
        : "r"(a0), "r"(a1), "r"(a2), "r"(a3), "r"(b0), "r"(b1))

__device__ __forceinline__ uint32_t pack_f16x2(float lo, float hi) {
    uint32_t u;
    // cvt.rn.f16x2.f32 d, a, b -> d.lo = cvt(b), d.hi = cvt(a)
    asm("cvt.rn.f16x2.f32 %0, %1, %2;" : "=r"(u) : "f"(hi), "f"(lo));
    return u;
}

// ============ problem constants ============
// etin[128 rows/tile, 256] * W1[256,128] -> relu -> * W2[128,64]. fp16 mma, fp32 accum.
// 512 threads = 16 warps (25% occ) as 8 row-groups x 2 N-halves.
// GEMM1 warp = 16 rows x 64 N-cols (acc 32 regs), H via SMEM,
// GEMM2 warp = 16 rows x 32 out-cols (acc 16 regs). 2 syncs/tile.

static constexpr int TILE_M = 128;
static constexpr int NTHREADS = 512;
static constexpr int SM_B1  = 0;         // 128 floats (512 B)
static constexpr int SM_B2  = 512;       // 64 floats  (256 B)
static constexpr int SM_W1T = 1024;      // W1^T [128 n][256 k] fp16, 512 B/row -> 64 KB
static constexpr int SM_W2T = SM_W1T + 65536;   // W2^T [64 n][128 k] fp16 -> 16 KB
static constexpr int SM_A   = SM_W2T + 16384;   // etin tile [128 row][256 k] fp16 -> 64 KB
static constexpr int SM_H   = SM_A + 65536;     // H tile [128 row][128 k] fp16 -> 32 KB
static constexpr int SMEM_TOTAL = SM_H + 32768; // 181248 B

// XOR swizzle on 16B chunk index within a row: phys_chunk = chunk ^ (row & 7).
// A rows are 512 B (32 chunks), H rows are 256 B (16 chunks) — conflict-free
// for ldmatrix (8 rows, same logical chunk) and the STS patterns below.

__global__ void __launch_bounds__(NTHREADS, 1)
edgeblock_kernel(const float* __restrict__ vdata, const float* __restrict__ edata,
                 const float* __restrict__ cdata, const float* __restrict__ W1,
                 const float* __restrict__ b1, const float* __restrict__ W2,
                 const float* __restrict__ b2, const int* __restrict__ snd,
                 const int* __restrict__ rcv, float* __restrict__ out,
                 int B, int Nn, int E, int tiles_per_batch, int total_tiles) {
    extern __shared__ char smem[];
    const uint32_t smem_base = smem_to_u32(smem);
    const int tid  = threadIdx.x;
    const int wid  = tid >> 5;
    const int lane = tid & 31;
    const int lr   = lane & 7;       // ldmatrix row-within-group
    const int sub  = lane >> 3;      // ldmatrix matrix index
    const int q    = lane & 3;       // mma col-pair selector
    const int rr   = lane >> 2;      // mma row-within-group
    const int slot = lane >> 3;      // gather: 8-lane unit id within warp
    const int L    = lane & 7;       // gather: lane within unit
    const int rg   = wid >> 1;       // row-group 0..7 (16 rows each)
    const int nh   = wid & 1;        // N-half 0..1
    const int mr0  = rg * 16;        // this warp's first row in the tile

    // ---- one-time: stage weights + biases into SMEM ----
    for (int idx = tid; idx < 256 * 128; idx += NTHREADS) {
        int k = idx >> 7, n = idx & 127;
        uint32_t c = (uint32_t)(k >> 3);
        uint32_t off = (uint32_t)n * 512u + ((c ^ (uint32_t)(n & 7)) << 4) + (uint32_t)(k & 7) * 2u;
        *reinterpret_cast<__half*>(smem + SM_W1T + off) = __float2half_rn(W1[idx]);
    }
    for (int idx = tid; idx < 128 * 64; idx += NTHREADS) {
        int k = idx >> 6, n = idx & 63;
        uint32_t c = (uint32_t)(k >> 3);
        uint32_t off = (uint32_t)n * 256u + ((c ^ (uint32_t)(n & 7)) << 4) + (uint32_t)(k & 7) * 2u;
        *reinterpret_cast<__half*>(smem + SM_W2T + off) = __float2half_rn(W2[idx]);
    }
    float* b1s = reinterpret_cast<float*>(smem + SM_B1);
    float* b2s = reinterpret_cast<float*>(smem + SM_B2);
    if (tid < 128) b1s[tid] = b1[tid];
    if (tid < 64)  b2s[tid] = b2[tid];
    __syncthreads();

    const float4* ef = reinterpret_cast<const float4*>(edata);
    const float4* vf = reinterpret_cast<const float4*>(vdata);
    const float4* cf = reinterpret_cast<const float4*>(cdata);

    for (int t = blockIdx.x; t < total_tiles; t += gridDim.x) {
        const int b  = t / tiles_per_batch;
        const int e0 = (t - b * tiles_per_batch) * TILE_M;

        // ---- coalesced gather with preloaded indices ----
        // Task p (0..7): unit u = wid*32 + p*4 + slot -> (row = u>>2, src = u&3).
        // Lane L of the 8-lane unit loads float4 [L] and [L+8] of the 64-float row.
        int idxv[8];
#pragma unroll
        for (int p = 0; p < 8; p++) {
            const int u   = wid * 32 + p * 4 + slot;
            const int row = u >> 2;
            const int src = u & 3;
            int e = e0 + row; if (e >= E) e = E - 1;
            const long long be = (long long)b * E + e;
            int v = 0;
            if (src == 1) v = snd[be];
            if (src == 2) v = rcv[be];
            idxv[p] = v;
        }
#pragma unroll
        for (int hh = 0; hh < 2; hh++) {
            uint2 pk[4][2];
#pragma unroll
            for (int p4 = 0; p4 < 4; p4++) {
                const int p   = hh * 4 + p4;
                const int u   = wid * 32 + p * 4 + slot;
                const int row = u >> 2;
                const int src = u & 3;
                int e = e0 + row; if (e >= E) e = E - 1;
                const long long be = (long long)b * E + e;
                const float4* base =
                    (src == 0) ? (ef + be * 16) :
                    (src == 3) ? (cf + (long long)b * 16)
                               : (vf + ((long long)b * Nn + idxv[p]) * 16);
                float4 v0 = base[L];
                float4 v1 = base[L + 8];
                pk[p4][0].x = pack_f16x2(v0.x, v0.y); pk[p4][0].y = pack_f16x2(v0.z, v0.w);
                pk[p4][1].x = pack_f16x2(v1.x, v1.y); pk[p4][1].y = pack_f16x2(v1.z, v1.w);
            }
#pragma unroll
            for (int p4 = 0; p4 < 4; p4++) {
                const int p   = hh * 4 + p4;
                const int u   = wid * 32 + p * 4 + slot;
                const int row = u >> 2;
                const int src = u & 3;
                const uint32_t rx = (uint32_t)(row & 7);
                const uint32_t c0 = (uint32_t)(src * 8 + (L >> 1));
                const uint32_t hoff = (uint32_t)(L & 1) * 8u;
                char* rp = smem + SM_A + (uint32_t)row * 512u;
                *reinterpret_cast<uint2*>(rp + ((c0 ^ rx) << 4) + hoff) = pk[p4][0];
                *reinterpret_cast<uint2*>(rp + (((c0 + 4) ^ rx) << 4) + hoff) = pk[p4][1];
            }
        }
        __syncthreads();  // sync1: A tile ready (and prev iter's H readers done)

        // ---- GEMM1: warp (rg,nh) -> H[16 rows, 64 N-cols], then STS to H buffer ----
        {
            float acc1[32];
#pragma unroll
            for (int i = 0; i < 32; i++) acc1[i] = 0.0f;

#pragma unroll
            for (int kc = 0; kc < 16; kc++) {
                const uint32_t achunk = (uint32_t)(kc * 2 + (sub >> 1));
                const int arow = mr0 + lr + ((sub & 1) << 3);
                const uint32_t aaddr = smem_base + SM_A + (uint32_t)arow * 512u
                                     + ((achunk ^ (uint32_t)(arow & 7)) << 4);
                uint32_t a0, a1, a2, a3;
                LDSM_X4(a0, a1, a2, a3, aaddr);
#pragma unroll
                for (int nt = 0; nt < 4; nt++) {
                    const int brow = nh * 64 + nt * 16 + lr + ((sub & 1) << 3);
                    const uint32_t baddr = smem_base + SM_W1T + (uint32_t)brow * 512u
                                         + ((achunk ^ (uint32_t)(brow & 7)) << 4);
                    uint32_t r0, r1, r2, r3;
                    LDSM_X4(r0, r1, r2, r3, baddr);
                    MMA_16816(&acc1[8 * nt],     a0, a1, a2, a3, r0, r2);
                    MMA_16816(&acc1[8 * nt + 4], a0, a1, a2, a3, r1, r3);
                }
            }

            // bias + relu -> fp16 -> STS into H buffer (swizzled, 256 B rows)
            const int hrow0 = mr0 + rr;      // rows rr and rr+8 within group
#pragma unroll
            for (int nt = 0; nt < 4; nt++) {
                const int c0 = nh * 64 + nt * 16 + q * 2;   // col of d0/d1
                float2 bb0 = *reinterpret_cast<const float2*>(b1s + c0);
                float2 bb1 = *reinterpret_cast<const float2*>(b1s + c0 + 8);
                float x0 = fmaxf(acc1[8 * nt]     + bb0.x, 0.0f);
                float x1 = fmaxf(acc1[8 * nt + 1] + bb0.y, 0.0f);
                float x2 = fmaxf(acc1[8 * nt + 2] + bb0.x, 0.0f);
                float x3 = fmaxf(acc1[8 * nt + 3] + bb0.y, 0.0f);
                float x4 = fmaxf(acc1[8 * nt + 4] + bb1.x, 0.0f);
                float x5 = fmaxf(acc1[8 * nt + 5] + bb1.y, 0.0f);
                float x6 = fmaxf(acc1[8 * nt + 6] + bb1.x, 0.0f);
                float x7 = fmaxf(acc1[8 * nt + 7] + bb1.y, 0.0f);
                const uint32_t ch0 = (uint32_t)(nh * 8 + nt * 2);     // chunk of c0
                {
                    const int hr = hrow0;
                    const uint32_t rx = (uint32_t)(hr & 7);
                    char* hp = smem + SM_H + (uint32_t)hr * 256u;
                    *reinterpret_cast<uint32_t*>(hp + ((ch0 ^ rx) << 4) + q * 4)       = pack_f16x2(x0, x1);
                    *reinterpret_cast<uint32_t*>(hp + (((ch0 + 1) ^ rx) << 4) + q * 4) = pack_f16x2(x4, x5);
                }
                {
                    const int hr = hrow0 + 8;
                    const uint32_t rx = (uint32_t)(hr & 7);
                    char* hp = smem + SM_H + (uint32_t)hr * 256u;
                    *reinterpret_cast<uint32_t*>(hp + ((ch0 ^ rx) << 4) + q * 4)       = pack_f16x2(x2, x3);
                    *reinterpret_cast<uint32_t*>(hp + (((ch0 + 1) ^ rx) << 4) + q * 4) = pack_f16x2(x6, x7);
                }
            }
        }
        __syncthreads();  // sync2: H complete; A free for next gather

        // ---- GEMM2: warp (rg,nh) -> O[16 rows, 32 out-cols] ----
        float acc2[16];
#pragma unroll
        for (int i = 0; i < 16; i++) acc2[i] = 0.0f;

#pragma unroll
        for (int kc = 0; kc < 8; kc++) {
            const uint32_t hchunk = (uint32_t)(kc * 2 + (sub >> 1));
            const int hrow = mr0 + lr + ((sub & 1) << 3);
            const uint32_t haddr = smem_base + SM_H + (uint32_t)hrow * 256u
                                 + ((hchunk ^ (uint32_t)(hrow & 7)) << 4);
            uint32_t h0, h1, h2, h3;
            LDSM_X4(h0, h1, h2, h3, haddr);
#pragma unroll
            for (int np = 0; np < 2; np++) {
                const int brow = nh * 32 + np * 16 + lr + ((sub & 1) << 3);
                const uint32_t baddr = smem_base + SM_W2T + (uint32_t)brow * 256u
                                     + ((hchunk ^ (uint32_t)(brow & 7)) << 4);
                uint32_t r0, r1, r2, r3;
                LDSM_X4(r0, r1, r2, r3, baddr);
                MMA_16816(&acc2[8 * np],     h0, h1, h2, h3, r0, r2);
                MMA_16816(&acc2[8 * np + 4], h0, h1, h2, h3, r1, r3);
            }
        }

        // ---- epilogue: + b2, store fp32 out[b, e, 32nh .. 32nh+31] ----
        {
            const int er0 = e0 + mr0 + rr;   // row for d0,d1
            const int er1 = er0 + 8;         // row for d2,d3
            const bool v0 = (er0 < E);
            const bool v1 = (er1 < E);
            float* o0 = out + ((long long)b * E + er0) * 64 + nh * 32 + q * 2;
            float* o1 = out + ((long long)b * E + er1) * 64 + nh * 32 + q * 2;
#pragma unroll
            for (int np = 0; np < 2; np++) {
#pragma unroll
                for (int chf = 0; chf < 2; chf++) {     // col offset 0 / +8
                    const int coff = np * 16 + chf * 8;
                    float2 bb = *reinterpret_cast<const float2*>(b2s + nh * 32 + coff + q * 2);
                    const int base = 8 * np + 4 * chf;
                    if (v0) {
                        float2 w; w.x = acc2[base]     + bb.x; w.y = acc2[base + 1] + bb.y;
                        *reinterpret_cast<float2*>(o0 + coff) = w;
                    }
                    if (v1) {
                        float2 w; w.x = acc2[base + 2] + bb.x; w.y = acc2[base + 3] + bb.y;
                        *reinterpret_cast<float2*>(o1 + coff) = w;
                    }
                }
            }
        }
    }
}

// ===================== launch =====================

extern "C" void kernel_launch(void* const* d_in, const int* in_sizes, int n_in,
                              void* d_out, int out_size) {
    (void)n_in; (void)out_size;
    const float* vdata = (const float*)d_in[0];
    const float* edata = (const float*)d_in[1];
    const float* cdata = (const float*)d_in[2];
    const float* W1    = (const float*)d_in[3];
    const float* b1    = (const float*)d_in[4];
    const float* W2    = (const float*)d_in[5];
    const float* b2    = (const float*)d_in[6];
    const int*   snd   = (const int*)d_in[7];
    const int*   rcv   = (const int*)d_in[8];
    float* out = (float*)d_out;

    int B  = in_sizes[2] / 64;          // cdata = B * 64
    int E  = in_sizes[7] / B;           // sender_ids = B * E
    int Nn = in_sizes[0] / (B * 64);    // vdata = B * N * 64

    int tiles_per_batch = (E + TILE_M - 1) / TILE_M;
    int total_tiles = B * tiles_per_batch;

    cudaFuncSetAttribute(edgeblock_kernel,
                         cudaFuncAttributeMaxDynamicSharedMemorySize, SMEM_TOTAL);

    int grid = 148;
    if (grid > total_tiles) grid = total_tiles;
    if (grid < 1) grid = 1;

    edgeblock_kernel<<<grid, NTHREADS, SMEM_TOTAL>>>(
        vdata, edata, cdata, W1, b1, W2, b2, snd, rcv, out,
        B, Nn, E, tiles_per_batch, total_tiles);
}

// round 16
// speedup vs baseline: 1.3714x; 1.3714x over previous
#include <cuda_runtime.h>
#include <cuda_fp16.h>
#include <cstdint>

// ============ target-safe warp-MMA primitives (sm_80+ features only) ============

__device__ __forceinline__ uint32_t smem_to_u32(const void* smem_ptr) {
    uint32_t addr;
    asm("{ .reg .u64 tmp; cvta.to.shared.u64 tmp, %1; cvt.u32.u64 %0, tmp; }"
        : "=r"(addr) : "l"(smem_ptr));
    return addr;
}

#define LDSM_X4(r0, r1, r2, r3, addr) \
    asm volatile("ldmatrix.sync.aligned.m8n8.x4.shared.b16 {%0,%1,%2,%3}, [%4];" \
        : "=r"(r0), "=r"(r1), "=r"(r2), "=r"(r3) : "r"(addr))

#define MMA_16816(d, a0, a1, a2, a3, b0, b1) \
    asm volatile("mma.sync.aligned.m16n8k16.row.col.f32.f16.f16.f32 " \
        "{%0,%1,%2,%3}, {%4,%5,%6,%7}, {%8,%9}, {%0,%1,%2,%3};" \
        : "+f"((d)[0]), "+f"((d)[1]), "+f"((d)[2]), "+f"((d)[3]) \
        : "r"(a0), "r"(a1), "r"(a2), "r"(a3), "r"(b0), "r"(b1))

__device__ __forceinline__ uint32_t pack_f16x2(float lo, float hi) {
    uint32_t u;
    // cvt.rn.f16x2.f32 d, a, b -> d.lo = cvt(b), d.hi = cvt(a)
    asm("cvt.rn.f16x2.f32 %0, %1, %2;" : "=r"(u) : "f"(hi), "f"(lo));
    return u;
}

// ============ problem constants ============
// etin[128 rows/tile, 256] * W1[256,128] -> relu -> * W2[128,64]. fp16 mma, fp32 accum.
// R11 skeleton (M=16/warp, 202-221 regs, no spill) + double-buffered A tile with
// COMPILE-TIME buffer bases (template<int ABASE>, loop unrolled x2) -> 1 sync/tile.
// Gather of tile t+1 runs after the epilogue of t, overlapping other warps' GEMM.

static constexpr int TILE_M = 128;
static constexpr int SM_B1  = 0;         // 128 floats (512 B)
static constexpr int SM_B2  = 512;       // 64 floats  (256 B)
static constexpr int SM_W1T = 1024;      // W1^T [128 n][256 k] fp16, 512 B/row -> 64 KB
static constexpr int SM_W2T = SM_W1T + 65536;   // W2^T [64 n][128 k] fp16 -> 16 KB
static constexpr int SM_A0  = SM_W2T + 16384;   // A tile buf0 -> 64 KB
static constexpr int SM_A1  = SM_A0 + 65536;    // A tile buf1 -> 64 KB
static constexpr int SMEM_TOTAL = SM_A1 + 65536;  // 214016 B

// XOR swizzle on 16B chunk index within a row: phys_chunk = chunk ^ (row & 7).
// Rows are multiples of 128 B, so ldmatrix (8 rows, same logical chunk) is conflict-free.

// ---- gather one tile into buffer ABASE (compile-time constant) ----
template<int ABASE>
static __device__ __forceinline__ void gather_tile_fn(
    char* smem, const float4* __restrict__ ef, const float4* __restrict__ vf,
    const float4* __restrict__ cf, const int* __restrict__ snd,
    const int* __restrict__ rcv, int b, int e0, int E, int Nn,
    int wid, int slot, int L)
{
    const long long bE = (long long)b * E;
    // Phase A: preload the 16 gather indices (independent LDGs).
    int idxv[16];
#pragma unroll
    for (int p = 0; p < 16; p++) {
        const int u   = wid * 64 + p * 4 + slot;
        const int row = u >> 2;
        const int src = u & 3;
        int e = e0 + row; if (e >= E) e = E - 1;
        const long long be = bE + e;
        int v = 0;
        if (src == 1) v = snd[be];
        if (src == 2) v = rcv[be];
        idxv[p] = v;
    }
    // Phase B: two batches of 8 tasks; 16 independent float4 loads per batch.
#pragma unroll
    for (int hh = 0; hh < 2; hh++) {
        uint2 pk[8][2];
#pragma unroll
        for (int p8 = 0; p8 < 8; p8++) {
            const int p   = hh * 8 + p8;
            const int u   = wid * 64 + p * 4 + slot;
            const int row = u >> 2;
            const int src = u & 3;
            int e = e0 + row; if (e >= E) e = E - 1;
            const long long be = bE + e;
            const float4* base =
                (src == 0) ? (ef + be * 16) :
                (src == 3) ? (cf + (long long)b * 16)
                           : (vf + ((long long)b * Nn + idxv[p]) * 16);
            float4 v0 = base[L];
            float4 v1 = base[L + 8];
            pk[p8][0].x = pack_f16x2(v0.x, v0.y); pk[p8][0].y = pack_f16x2(v0.z, v0.w);
            pk[p8][1].x = pack_f16x2(v1.x, v1.y); pk[p8][1].y = pack_f16x2(v1.z, v1.w);
        }
#pragma unroll
        for (int p8 = 0; p8 < 8; p8++) {
            const int p   = hh * 8 + p8;
            const int u   = wid * 64 + p * 4 + slot;
            const int row = u >> 2;
            const int src = u & 3;
            const uint32_t rx = (uint32_t)(row & 7);
            const uint32_t c0 = (uint32_t)(src * 8 + (L >> 1));
            const uint32_t hoff = (uint32_t)(L & 1) * 8u;
            char* rp = smem + ABASE + (uint32_t)row * 512u;
            *reinterpret_cast<uint2*>(rp + ((c0 ^ rx) << 4) + hoff) = pk[p8][0];
            *reinterpret_cast<uint2*>(rp + (((c0 + 4) ^ rx) << 4) + hoff) = pk[p8][1];
        }
    }
}

// ---- process one tile from buffer ABASE: GEMM1 -> relu -> GEMM2 -> store ----
template<int ABASE>
static __device__ __forceinline__ void process_tile_fn(
    uint32_t smem_base, const float* __restrict__ b1s, const float* __restrict__ b2s,
    float* __restrict__ out, int b, int e0, int E,
    int m0, int lr, int sub, int q, int rr)
{
    // GEMM1: H[16,128] = A[16,256] @ W1 (per warp)
    float acc1[64];
#pragma unroll
    for (int i = 0; i < 64; i++) acc1[i] = 0.0f;

#pragma unroll
    for (int kc = 0; kc < 16; kc++) {
        const int arow = m0 + lr + ((sub & 1) << 3);
        const uint32_t achunk = (uint32_t)(kc * 2 + (sub >> 1));
        const uint32_t aaddr = smem_base + ABASE + (uint32_t)arow * 512u
                             + ((achunk ^ (uint32_t)(arow & 7)) << 4);
        uint32_t a0, a1, a2, a3;
        LDSM_X4(a0, a1, a2, a3, aaddr);
#pragma unroll
        for (int nt = 0; nt < 8; nt++) {
            const int brow = nt * 16 + lr + ((sub & 1) << 3);
            const uint32_t baddr = smem_base + SM_W1T + (uint32_t)brow * 512u
                                 + ((achunk ^ (uint32_t)(brow & 7)) << 4);
            uint32_t r0, r1, r2, r3;
            LDSM_X4(r0, r1, r2, r3, baddr);
            MMA_16816(&acc1[8 * nt],     a0, a1, a2, a3, r0, r2);
            MMA_16816(&acc1[8 * nt + 4], a0, a1, a2, a3, r1, r3);
        }
    }

    // bias + relu -> fp16 H fragments (become GEMM2 A fragments)
    uint32_t h[32];
#pragma unroll
    for (int j = 0; j < 16; j++) {
        float2 bb = *reinterpret_cast<const float2*>(b1s + j * 8 + q * 2);
        float x0 = fmaxf(acc1[4 * j]     + bb.x, 0.0f);
        float x1 = fmaxf(acc1[4 * j + 1] + bb.y, 0.0f);
        float x2 = fmaxf(acc1[4 * j + 2] + bb.x, 0.0f);
        float x3 = fmaxf(acc1[4 * j + 3] + bb.y, 0.0f);
        h[2 * j]     = pack_f16x2(x0, x1);  // row rr
        h[2 * j + 1] = pack_f16x2(x2, x3);  // row rr+8
    }

    // GEMM2: O[16,64] = H[16,128] @ W2
    float acc2[32];
#pragma unroll
    for (int i = 0; i < 32; i++) acc2[i] = 0.0f;

#pragma unroll
    for (int kc = 0; kc < 8; kc++) {
        const uint32_t bchunk = (uint32_t)(kc * 2 + (sub >> 1));
#pragma unroll
        for (int np = 0; np < 4; np++) {  // pairs of 8-col n-tiles
            const int brow = np * 16 + lr + ((sub & 1) << 3);
            const uint32_t baddr = smem_base + SM_W2T + (uint32_t)brow * 256u
                                 + ((bchunk ^ (uint32_t)(brow & 7)) << 4);
            uint32_t r0, r1, r2, r3;
            LDSM_X4(r0, r1, r2, r3, baddr);
            MMA_16816(&acc2[8 * np],     h[4 * kc], h[4 * kc + 1], h[4 * kc + 2], h[4 * kc + 3], r0, r2);
            MMA_16816(&acc2[8 * np + 4], h[4 * kc], h[4 * kc + 1], h[4 * kc + 2], h[4 * kc + 3], r1, r3);
        }
    }

    // epilogue: + b2, store fp32 out[b, e, 0:64]
    const int er0 = e0 + m0 + rr;       // row for c0,c1
    const int er1 = er0 + 8;            // row for c2,c3
    const bool v0 = (er0 < E);
    const bool v1 = (er1 < E);
    float* o0 = out + ((long long)b * E + er0) * 64 + q * 2;
    float* o1 = out + ((long long)b * E + er1) * 64 + q * 2;
#pragma unroll
    for (int j = 0; j < 8; j++) {
        float2 bb = *reinterpret_cast<const float2*>(b2s + j * 8 + q * 2);
        if (v0) {
            float2 w; w.x = acc2[4 * j] + bb.x; w.y = acc2[4 * j + 1] + bb.y;
            *reinterpret_cast<float2*>(o0 + j * 8) = w;
        }
        if (v1) {
            float2 w; w.x = acc2[4 * j + 2] + bb.x; w.y = acc2[4 * j + 3] + bb.y;
            *reinterpret_cast<float2*>(o1 + j * 8) = w;
        }
    }
}

__global__ void __launch_bounds__(256, 1)
edgeblock_kernel(const float* __restrict__ vdata, const float* __restrict__ edata,
                 const float* __restrict__ cdata, const float* __restrict__ W1,
                 const float* __restrict__ b1, const float* __restrict__ W2,
                 const float* __restrict__ b2, const int* __restrict__ snd,
                 const int* __restrict__ rcv, float* __restrict__ out,
                 int B, int Nn, int E, int tiles_per_batch, int total_tiles) {
    extern __shared__ char smem[];
    const uint32_t smem_base = smem_to_u32(smem);
    const int tid  = threadIdx.x;
    const int wid  = tid >> 5;
    const int lane = tid & 31;
    const int lr   = lane & 7;       // ldmatrix row-within-group
    const int sub  = lane >> 3;      // ldmatrix matrix index
    const int q    = lane & 3;       // mma col-pair selector
    const int rr   = lane >> 2;      // mma row-within-group
    const int slot = lane >> 3;      // gather: 8-lane unit id within warp
    const int L    = lane & 7;       // gather: lane within unit

    // ---- one-time: stage weights + biases into SMEM ----
    for (int idx = tid; idx < 256 * 128; idx += 256) {
        int k = idx >> 7, n = idx & 127;
        uint32_t c = (uint32_t)(k >> 3);
        uint32_t off = (uint32_t)n * 512u + ((c ^ (uint32_t)(n & 7)) << 4) + (uint32_t)(k & 7) * 2u;
        *reinterpret_cast<__half*>(smem + SM_W1T + off) = __float2half_rn(W1[idx]);
    }
    for (int idx = tid; idx < 128 * 64; idx += 256) {
        int k = idx >> 6, n = idx & 63;
        uint32_t c = (uint32_t)(k >> 3);
        uint32_t off = (uint32_t)n * 256u + ((c ^ (uint32_t)(n & 7)) << 4) + (uint32_t)(k & 7) * 2u;
        *reinterpret_cast<__half*>(smem + SM_W2T + off) = __float2half_rn(W2[idx]);
    }
    float* b1s = reinterpret_cast<float*>(smem + SM_B1);
    float* b2s = reinterpret_cast<float*>(smem + SM_B2);
    if (tid < 128) b1s[tid] = b1[tid];
    if (tid < 64)  b2s[tid] = b2[tid];

    const int m0 = wid * 16;  // this warp's 16 rows within the tile
    const float4* ef = reinterpret_cast<const float4*>(edata);
    const float4* vf = reinterpret_cast<const float4*>(vdata);
    const float4* cf = reinterpret_cast<const float4*>(cdata);
    const int G = gridDim.x;

    // ---- prologue: fill buf0 with this CTA's first tile ----
    int t = blockIdx.x;
    if (t < total_tiles) {
        const int b0 = t / tiles_per_batch;
        gather_tile_fn<SM_A0>(smem, ef, vf, cf, snd, rcv,
                              b0, (t - b0 * tiles_per_batch) * TILE_M, E, Nn, wid, slot, L);
    }

    // Pair-unrolled main loop: one __syncthreads per tile, static buffer bases.
    while (t < total_tiles) {
        __syncthreads();   // buf0 gather visible; prior buf0 readers done
        {
            const int b  = t / tiles_per_batch;
            const int e0 = (t - b * tiles_per_batch) * TILE_M;
            process_tile_fn<SM_A0>(smem_base, b1s, b2s, out, b, e0, E, m0, lr, sub, q, rr);
            const int tn = t + G;
            if (tn < total_tiles) {
                const int bn = tn / tiles_per_batch;
                gather_tile_fn<SM_A1>(smem, ef, vf, cf, snd, rcv,
                                      bn, (tn - bn * tiles_per_batch) * TILE_M, E, Nn, wid, slot, L);
            }
        }
        t += G;
        if (t >= total_tiles) break;

        __syncthreads();   // buf1 gather visible; prior buf1 readers done
        {
            const int b  = t / tiles_per_batch;
            const int e0 = (t - b * tiles_per_batch) * TILE_M;
            process_tile_fn<SM_A1>(smem_base, b1s, b2s, out, b, e0, E, m0, lr, sub, q, rr);
            const int tn = t + G;
            if (tn < total_tiles) {
                const int bn = tn / tiles_per_batch;
                gather_tile_fn<SM_A0>(smem, ef, vf, cf, snd, rcv,
                                      bn, (tn - bn * tiles_per_batch) * TILE_M, E, Nn, wid, slot, L);
            }
        }
        t += G;
    }
}

// ===================== launch =====================

extern "C" void kernel_launch(void* const* d_in, const int* in_sizes, int n_in,
                              void* d_out, int out_size) {
    (void)n_in; (void)out_size;
    const float* vdata = (const float*)d_in[0];
    const float* edata = (const float*)d_in[1];
    const float* cdata = (const float*)d_in[2];
    const float* W1    = (const float*)d_in[3];
    const float* b1    = (const float*)d_in[4];
    const float* W2    = (const float*)d_in[5];
    const float* b2    = (const float*)d_in[6];
    const int*   snd   = (const int*)d_in[7];
    const int*   rcv   = (const int*)d_in[8];
    float* out = (float*)d_out;

    int B  = in_sizes[2] / 64;          // cdata = B * 64
    int E  = in_sizes[7] / B;           // sender_ids = B * E
    int Nn = in_sizes[0] / (B * 64);    // vdata = B * N * 64

    int tiles_per_batch = (E + TILE_M - 1) / TILE_M;
    int total_tiles = B * tiles_per_batch;

    cudaFuncSetAttribute(edgeblock_kernel,
                         cudaFuncAttributeMaxDynamicSharedMemorySize, SMEM_TOTAL);

    int grid = 148;
    if (grid > total_tiles) grid = total_tiles;
    if (grid < 1) grid = 1;

    edgeblock_kernel<<<grid, 256, SMEM_TOTAL>>>(
        vdata, edata, cdata, W1, b1, W2, b2, snd, rcv, out,
        B, Nn, E, tiles_per_batch, total_tiles);
}

// round 17
// speedup vs baseline: 1.5268x; 1.1133x over previous
#include <cuda_runtime.h>
#include <cuda_fp16.h>
#include <cstdint>

// ============ target-safe warp-MMA primitives (sm_80+ features only) ============

__device__ __forceinline__ uint32_t smem_to_u32(const void* smem_ptr) {
    uint32_t addr;
    asm("{ .reg .u64 tmp; cvta.to.shared.u64 tmp, %1; cvt.u32.u64 %0, tmp; }"
        : "=r"(addr) : "l"(smem_ptr));
    return addr;
}

#define LDSM_X4(r0, r1, r2, r3, addr) \
    asm volatile("ldmatrix.sync.aligned.m8n8.x4.shared.b16 {%0,%1,%2,%3}, [%4];" \
        : "=r"(r0), "=r"(r1), "=r"(r2), "=r"(r3) : "r"(addr))

#define MMA_16816(d, a0, a1, a2, a3, b0, b1) \
    asm volatile("mma.sync.aligned.m16n8k16.row.col.f32.f16.f16.f32 " \
        "{%0,%1,%2,%3}, {%4,%5,%6,%7}, {%8,%9}, {%0,%1,%2,%3};" \
        : "+f"((d)[0]), "+f"((d)[1]), "+f"((d)[2]), "+f"((d)[3]) \
        : "r"(a0), "r"(a1), "r"(a2), "r"(a3), "r"(b0), "r"(b1))

__device__ __forceinline__ uint32_t pack_f16x2(float lo, float hi) {
    uint32_t u;
    // cvt.rn.f16x2.f32 d, a, b -> d.lo = cvt(b), d.hi = cvt(a)
    asm("cvt.rn.f16x2.f32 %0, %1, %2;" : "=r"(u) : "f"(hi), "f"(lo));
    return u;
}

// ============ problem constants ============
// etin[64 rows/tile, 256] * W1[256,128] -> relu -> * W2[128,64]. fp16 mma, fp32 accum.
// R11 per-warp code verbatim; CTA halved to 128 threads / TILE_M=64 so TWO CTAs
// co-reside per SM (2 x 115712 B SMEM + reserved = 228 KB carveout exactly).
// Independent CTA barriers overlap one CTA's gather with the other's GEMM.

static constexpr int TILE_M = 64;
static constexpr int NTHREADS = 128;
static constexpr int SM_B1  = 0;         // 128 floats (512 B)
static constexpr int SM_B2  = 512;       // 64 floats  (256 B)
static constexpr int SM_W1T = 1024;      // W1^T [128 n][256 k] fp16, 512 B/row -> 64 KB
static constexpr int SM_W2T = SM_W1T + 65536;   // W2^T [64 n][128 k] fp16 -> 16 KB
static constexpr int SM_A   = SM_W2T + 16384;   // etin tile [64 row][256 k] fp16 -> 32 KB
static constexpr int SMEM_TOTAL = SM_A + TILE_M * 512; // 115712 B

// XOR swizzle on 16B chunk index within a row: phys_chunk = chunk ^ (row & 7).
// Rows are multiples of 128 B, so ldmatrix (8 rows, same logical chunk) is conflict-free.

__global__ void __launch_bounds__(NTHREADS, 2)
edgeblock_kernel(const float* __restrict__ vdata, const float* __restrict__ edata,
                 const float* __restrict__ cdata, const float* __restrict__ W1,
                 const float* __restrict__ b1, const float* __restrict__ W2,
                 const float* __restrict__ b2, const int* __restrict__ snd,
                 const int* __restrict__ rcv, float* __restrict__ out,
                 int B, int Nn, int E, int tiles_per_batch, int total_tiles) {
    extern __shared__ char smem[];
    const uint32_t smem_base = smem_to_u32(smem);
    const int tid  = threadIdx.x;
    const int wid  = tid >> 5;
    const int lane = tid & 31;
    const int lr   = lane & 7;       // ldmatrix row-within-group
    const int sub  = lane >> 3;      // ldmatrix matrix index
    const int q    = lane & 3;       // mma col-pair selector
    const int rr   = lane >> 2;      // mma row-within-group
    const int slot = lane >> 3;      // gather: 8-lane unit id within warp
    const int L    = lane & 7;       // gather: lane within unit

    // ---- one-time: stage weights + biases into SMEM ----
    for (int idx = tid; idx < 256 * 128; idx += NTHREADS) {
        int k = idx >> 7, n = idx & 127;
        uint32_t c = (uint32_t)(k >> 3);
        uint32_t off = (uint32_t)n * 512u + ((c ^ (uint32_t)(n & 7)) << 4) + (uint32_t)(k & 7) * 2u;
        *reinterpret_cast<__half*>(smem + SM_W1T + off) = __float2half_rn(W1[idx]);
    }
    for (int idx = tid; idx < 128 * 64; idx += NTHREADS) {
        int k = idx >> 6, n = idx & 63;
        uint32_t c = (uint32_t)(k >> 3);
        uint32_t off = (uint32_t)n * 256u + ((c ^ (uint32_t)(n & 7)) << 4) + (uint32_t)(k & 7) * 2u;
        *reinterpret_cast<__half*>(smem + SM_W2T + off) = __float2half_rn(W2[idx]);
    }
    float* b1s = reinterpret_cast<float*>(smem + SM_B1);
    float* b2s = reinterpret_cast<float*>(smem + SM_B2);
    if (tid < 128) b1s[tid] = b1[tid];
    if (tid < 64)  b2s[tid] = b2[tid];
    __syncthreads();

    const int m0 = wid * 16;  // this warp's 16 rows within the tile
    const float4* ef = reinterpret_cast<const float4*>(edata);
    const float4* vf = reinterpret_cast<const float4*>(vdata);
    const float4* cf = reinterpret_cast<const float4*>(cdata);

    for (int t = blockIdx.x; t < total_tiles; t += gridDim.x) {
        const int b  = t / tiles_per_batch;
        const int e0 = (t - b * tiles_per_batch) * TILE_M;

        // ---- coalesced gather with preloaded indices ----
        // Task p (0..15): unit u = wid*64 + p*4 + slot -> (row = u>>2, src = u&3);
        // wid 0..3 covers units 0..255 = 64 rows x 4 sources.
        int idxv[16];
#pragma unroll
        for (int p = 0; p < 16; p++) {
            const int u   = wid * 64 + p * 4 + slot;
            const int row = u >> 2;
            const int src = u & 3;
            int e = e0 + row; if (e >= E) e = E - 1;
            const long long be = (long long)b * E + e;
            int v = 0;
            if (src == 1) v = snd[be];
            if (src == 2) v = rcv[be];
            idxv[p] = v;
        }
#pragma unroll
        for (int hh = 0; hh < 2; hh++) {
            uint2 pk[8][2];
#pragma unroll
            for (int p8 = 0; p8 < 8; p8++) {
                const int p   = hh * 8 + p8;
                const int u   = wid * 64 + p * 4 + slot;
                const int row = u >> 2;
                const int src = u & 3;
                int e = e0 + row; if (e >= E) e = E - 1;
                const long long be = (long long)b * E + e;
                const float4* base =
                    (src == 0) ? (ef + be * 16) :
                    (src == 3) ? (cf + (long long)b * 16)
                               : (vf + ((long long)b * Nn + idxv[p]) * 16);
                float4 v0 = base[L];
                float4 v1 = base[L + 8];
                pk[p8][0].x = pack_f16x2(v0.x, v0.y); pk[p8][0].y = pack_f16x2(v0.z, v0.w);
                pk[p8][1].x = pack_f16x2(v1.x, v1.y); pk[p8][1].y = pack_f16x2(v1.z, v1.w);
            }
#pragma unroll
            for (int p8 = 0; p8 < 8; p8++) {
                const int p   = hh * 8 + p8;
                const int u   = wid * 64 + p * 4 + slot;
                const int row = u >> 2;
                const int src = u & 3;
                const uint32_t rx = (uint32_t)(row & 7);
                const uint32_t c0 = (uint32_t)(src * 8 + (L >> 1));
                const uint32_t hoff = (uint32_t)(L & 1) * 8u;
                char* rp = smem + SM_A + (uint32_t)row * 512u;
                *reinterpret_cast<uint2*>(rp + ((c0 ^ rx) << 4) + hoff) = pk[p8][0];
                *reinterpret_cast<uint2*>(rp + (((c0 + 4) ^ rx) << 4) + hoff) = pk[p8][1];
            }
        }
        __syncthreads();

        // ---- GEMM1: H[16,128] = A[16,256] @ W1  (per warp) ----
        float acc1[64];
#pragma unroll
        for (int i = 0; i < 64; i++) acc1[i] = 0.0f;

#pragma unroll
        for (int kc = 0; kc < 16; kc++) {
            const int arow = m0 + lr + ((sub & 1) << 3);
            const uint32_t achunk = (uint32_t)(kc * 2 + (sub >> 1));
            const uint32_t aaddr = smem_base + SM_A + (uint32_t)arow * 512u
                                 + ((achunk ^ (uint32_t)(arow & 7)) << 4);
            uint32_t a0, a1, a2, a3;
            LDSM_X4(a0, a1, a2, a3, aaddr);
#pragma unroll
            for (int nt = 0; nt < 8; nt++) {
                const int brow = nt * 16 + lr + ((sub & 1) << 3);
                const uint32_t baddr = smem_base + SM_W1T + (uint32_t)brow * 512u
                                     + ((achunk ^ (uint32_t)(brow & 7)) << 4);
                uint32_t r0, r1, r2, r3;
                LDSM_X4(r0, r1, r2, r3, baddr);
                MMA_16816(&acc1[8 * nt],     a0, a1, a2, a3, r0, r2);
                MMA_16816(&acc1[8 * nt + 4], a0, a1, a2, a3, r1, r3);
            }
        }
        __syncthreads();  // all A-tile reads done; next gather may overwrite

        // ---- bias + relu -> fp16 H fragments (become GEMM2 A fragments) ----
        uint32_t h[32];
#pragma unroll
        for (int j = 0; j < 16; j++) {
            float2 bb = *reinterpret_cast<const float2*>(b1s + j * 8 + q * 2);
            float x0 = fmaxf(acc1[4 * j]     + bb.x, 0.0f);
            float x1 = fmaxf(acc1[4 * j + 1] + bb.y, 0.0f);
            float x2 = fmaxf(acc1[4 * j + 2] + bb.x, 0.0f);
            float x3 = fmaxf(acc1[4 * j + 3] + bb.y, 0.0f);
            h[2 * j]     = pack_f16x2(x0, x1);  // row rr
            h[2 * j + 1] = pack_f16x2(x2, x3);  // row rr+8
        }

        // ---- GEMM2: O[16,64] = H[16,128] @ W2 ----
        float acc2[32];
#pragma unroll
        for (int i = 0; i < 32; i++) acc2[i] = 0.0f;

#pragma unroll
        for (int kc = 0; kc < 8; kc++) {
            const uint32_t bchunk = (uint32_t)(kc * 2 + (sub >> 1));
#pragma unroll
            for (int np = 0; np < 4; np++) {  // pairs of 8-col n-tiles
                const int brow = np * 16 + lr + ((sub & 1) << 3);
                const uint32_t baddr = smem_base + SM_W2T + (uint32_t)brow * 256u
                                     + ((bchunk ^ (uint32_t)(brow & 7)) << 4);
                uint32_t r0, r1, r2, r3;
                LDSM_X4(r0, r1, r2, r3, baddr);
                MMA_16816(&acc2[8 * np],     h[4 * kc], h[4 * kc + 1], h[4 * kc + 2], h[4 * kc + 3], r0, r2);
                MMA_16816(&acc2[8 * np + 4], h[4 * kc], h[4 * kc + 1], h[4 * kc + 2], h[4 * kc + 3], r1, r3);
            }
        }

        // ---- epilogue: + b2, store fp32 out[b, e, 0:64] ----
        {
            const int er0 = e0 + m0 + rr;       // row for c0,c1
            const int er1 = er0 + 8;            // row for c2,c3
            const bool v0 = (er0 < E);
            const bool v1 = (er1 < E);
            float* o0 = out + ((long long)b * E + er0) * 64 + q * 2;
            float* o1 = out + ((long long)b * E + er1) * 64 + q * 2;
#pragma unroll
            for (int j = 0; j < 8; j++) {
                float2 bb = *reinterpret_cast<const float2*>(b2s + j * 8 + q * 2);
                if (v0) {
                    float2 w; w.x = acc2[4 * j] + bb.x; w.y = acc2[4 * j + 1] + bb.y;
                    *reinterpret_cast<float2*>(o0 + j * 8) = w;
                }
                if (v1) {
                    float2 w; w.x = acc2[4 * j + 2] + bb.x; w.y = acc2[4 * j + 3] + bb.y;
                    *reinterpret_cast<float2*>(o1 + j * 8) = w;
                }
            }
        }
    }
}

// ===================== launch =====================

extern "C" void kernel_launch(void* const* d_in, const int* in_sizes, int n_in,
                              void* d_out, int out_size) {
    (void)n_in; (void)out_size;
    const float* vdata = (const float*)d_in[0];
    const float* edata = (const float*)d_in[1];
    const float* cdata = (const float*)d_in[2];
    const float* W1    = (const float*)d_in[3];
    const float* b1    = (const float*)d_in[4];
    const float* W2    = (const float*)d_in[5];
    const float* b2    = (const float*)d_in[6];
    const int*   snd   = (const int*)d_in[7];
    const int*   rcv   = (const int*)d_in[8];
    float* out = (float*)d_out;

    int B  = in_sizes[2] / 64;          // cdata = B * 64
    int E  = in_sizes[7] / B;           // sender_ids = B * E
    int Nn = in_sizes[0] / (B * 64);    // vdata = B * N * 64

    int tiles_per_batch = (E + TILE_M - 1) / TILE_M;
    int total_tiles = B * tiles_per_batch;

    cudaFuncSetAttribute(edgeblock_kernel,
                         cudaFuncAttributeMaxDynamicSharedMemorySize, SMEM_TOTAL);

    int grid = 296;  // 2 CTAs per SM
    if (grid > total_tiles) grid = total_tiles;
    if (grid < 1) grid = 1;

    edgeblock_kernel<<<grid, NTHREADS, SMEM_TOTAL>>>(
        vdata, edata, cdata, W1, b1, W2, b2, snd, rcv, out,
        B, Nn, E, tiles_per_batch, total_tiles);
}